// round 3
// baseline (speedup 1.0000x reference)
#include <cuda_runtime.h>
#include <math.h>

// ---------------- problem constants ----------------
#define BB   2
#define SS   2048
#define DD   2048
#define HH   16
#define HKVN 4
#define GRP  4          // HH / HKVN
#define RQ   1024
#define RKV  512
#define DR   64
#define DN   128
#define DHH  192        // DR + DN
#define DVV  128
#define MM   (BB*SS)    // 4096 rows

// ---------------- scratch (device globals; no allocation allowed) ---------
__device__ float g_qa [MM*RQ];
__device__ float g_qn [MM*RQ];
__device__ float g_qb [MM*HH*DHH];
__device__ float g_kva[MM*(RKV+DR)];
__device__ float g_kvn[MM*RKV];
__device__ float g_kvb[MM*HKVN*(DN+DVV)];
__device__ float g_Q  [(long)BB*HH*SS*DHH];
__device__ float g_K  [(long)BB*HKVN*SS*DHH];
__device__ float g_V  [(long)BB*HKVN*SS*DVV];
__device__ float g_AO [MM*HH*DVV];

// ---------------- SGEMM: C[M,N] = A[M,K] @ B[K,N] + bias ----------------
// 128x128 block, BK=8, 256 threads, 8x8 microtile, double-buffered smem.
// Requires: M % 128 == 0, K % 8 == 0 (N bound guarded).
__global__ void __launch_bounds__(256) sgemm_bias(
    const float* __restrict__ A, const float* __restrict__ Bm,
    const float* __restrict__ bias, float* __restrict__ C,
    int M, int N, int K)
{
    __shared__ float As[2][8][132];   // As[buf][k][m]
    __shared__ float Bs[2][8][128];   // Bs[buf][k][n]

    const int tid = threadIdx.x;
    const int bm  = blockIdx.y * 128;
    const int bn  = blockIdx.x * 128;
    const int tx  = tid & 15;
    const int ty  = tid >> 4;

    const int arow = tid >> 1;          // 0..127
    const int acol = (tid & 1) * 4;     // 0 / 4
    const int brow = tid >> 5;          // 0..7
    const int bcol = (tid & 31) * 4;    // 0..124

    const long Abase = (long)(bm + arow) * K + acol;
    const bool bok = (bn + bcol < N);

    float acc[8][8];
#pragma unroll
    for (int i = 0; i < 8; i++)
#pragma unroll
        for (int j = 0; j < 8; j++) acc[i][j] = 0.f;

    // prologue: load tile 0 into buf 0
    {
        float4 av = *(const float4*)&A[Abase];
        float4 bv = make_float4(0.f,0.f,0.f,0.f);
        if (bok) bv = *(const float4*)&Bm[(long)brow * N + bn + bcol];
        As[0][acol + 0][arow] = av.x;
        As[0][acol + 1][arow] = av.y;
        As[0][acol + 2][arow] = av.z;
        As[0][acol + 3][arow] = av.w;
        *(float4*)&Bs[0][brow][bcol] = bv;
    }
    __syncthreads();

    int buf = 0;
    for (int k0 = 8; k0 <= K; k0 += 8) {
        const bool more = (k0 < K);
        float4 av_n, bv_n;
        if (more) {
            av_n = *(const float4*)&A[Abase + k0];
            bv_n = make_float4(0.f,0.f,0.f,0.f);
            if (bok) bv_n = *(const float4*)&Bm[(long)(k0 + brow) * N + bn + bcol];
        }

#pragma unroll
        for (int kk = 0; kk < 8; kk++) {
            float4 a0 = *(float4*)&As[buf][kk][ty * 8];
            float4 a1 = *(float4*)&As[buf][kk][ty * 8 + 4];
            float4 b0 = *(float4*)&Bs[buf][kk][tx * 8];
            float4 b1 = *(float4*)&Bs[buf][kk][tx * 8 + 4];
            float af[8] = {a0.x,a0.y,a0.z,a0.w,a1.x,a1.y,a1.z,a1.w};
            float bf[8] = {b0.x,b0.y,b0.z,b0.w,b1.x,b1.y,b1.z,b1.w};
#pragma unroll
            for (int i = 0; i < 8; i++)
#pragma unroll
                for (int j = 0; j < 8; j++)
                    acc[i][j] += af[i] * bf[j];
        }

        if (more) {
            int nb = buf ^ 1;
            As[nb][acol + 0][arow] = av_n.x;
            As[nb][acol + 1][arow] = av_n.y;
            As[nb][acol + 2][arow] = av_n.z;
            As[nb][acol + 3][arow] = av_n.w;
            *(float4*)&Bs[nb][brow][bcol] = bv_n;
            __syncthreads();
            buf = nb;
        }
    }

#pragma unroll
    for (int i = 0; i < 8; i++) {
        long r = bm + ty * 8 + i;
#pragma unroll
        for (int j = 0; j < 8; j++) {
            int c = bn + tx * 8 + j;
            if (c < N) C[r * N + c] = acc[i][j] + bias[c];
        }
    }
}

// ---------------- RMSNorm (per row) ----------------
__global__ void __launch_bounds__(256) rmsnorm_k(
    const float* __restrict__ in, int inStride,
    const float* __restrict__ g, float* __restrict__ out, int L)
{
    const long row = blockIdx.x;
    const float* x = in + row * inStride;
    float s = 0.f;
    for (int i = threadIdx.x; i < L; i += 256) { float v = x[i]; s += v * v; }
#pragma unroll
    for (int o = 16; o > 0; o >>= 1) s += __shfl_xor_sync(0xffffffffu, s, o);
    __shared__ float red[8];
    if ((threadIdx.x & 31) == 0) red[threadIdx.x >> 5] = s;
    __syncthreads();
    float tot = 0.f;
#pragma unroll
    for (int i = 0; i < 8; i++) tot += red[i];
    const float sc = rsqrtf(tot / (float)L + 1e-20f);
    for (int i = threadIdx.x; i < L; i += 256)
        out[row * L + i] = x[i] * sc * g[i];
}

// ---------------- RoPE helpers / layout builders ----------------
__device__ __forceinline__ void rope_cs(int s, int j, float& c, float& sn) {
    float inv = (float)exp(-(double)j / 32.0 * log(10000.0));
    float a = (float)s * inv;
    c = cosf(a); sn = sinf(a);
}

__global__ void build_q_rope(const float* __restrict__ qb, float* __restrict__ Q)
{
    int idx = blockIdx.x * blockDim.x + threadIdx.x;
    if (idx >= BB * HH * SS * 32) return;
    int j = idx & 31; int t = idx >> 5;
    int s = t % SS; int t2 = t / SS;
    int h = t2 % HH; int b = t2 / HH;
    long base = (long)(b * SS + s) * (HH * DHH) + h * DHH;
    float x1 = qb[base + DN + j];
    float x2 = qb[base + DN + 32 + j];
    float c, sn; rope_cs(s, j, c, sn);
    long qo = ((long)(b * HH + h) * SS + s) * DHH;
    Q[qo + j]      = x1 * c - x2 * sn;
    Q[qo + 32 + j] = x2 * c + x1 * sn;
}

__global__ void build_q_nrope(const float* __restrict__ qb, float* __restrict__ Q)
{
    int idx = blockIdx.x * blockDim.x + threadIdx.x;
    if (idx >= BB * HH * SS * 128) return;
    int d = idx & 127; int t = idx >> 7;
    int s = t % SS; int t2 = t / SS;
    int h = t2 % HH; int b = t2 / HH;
    long base = (long)(b * SS + s) * (HH * DHH) + h * DHH;
    long qo = ((long)(b * HH + h) * SS + s) * DHH;
    Q[qo + 64 + d] = qb[base + d];
}

__global__ void build_k_rope(const float* __restrict__ kva, float* __restrict__ K)
{
    int idx = blockIdx.x * blockDim.x + threadIdx.x;
    if (idx >= BB * HKVN * SS * 32) return;
    int j = idx & 31; int t = idx >> 5;
    int s = t % SS; int t2 = t / SS;
    int h = t2 % HKVN; int b = t2 / HKVN;
    long base = (long)(b * SS + s) * (RKV + DR) + RKV;
    float x1 = kva[base + j];
    float x2 = kva[base + 32 + j];
    float c, sn; rope_cs(s, j, c, sn);
    long ko = ((long)(b * HKVN + h) * SS + s) * DHH;
    K[ko + j]      = x1 * c - x2 * sn;
    K[ko + 32 + j] = x2 * c + x1 * sn;
}

__global__ void build_kv(const float* __restrict__ kvb,
                         float* __restrict__ K, float* __restrict__ V)
{
    int idx = blockIdx.x * blockDim.x + threadIdx.x;
    if (idx >= BB * HKVN * SS * 256) return;
    int d = idx & 255; int t = idx >> 8;
    int s = t % SS; int t2 = t / SS;
    int h = t2 % HKVN; int b = t2 / HKVN;
    float v = kvb[(long)(b * SS + s) * (HKVN * 256) + h * 256 + d];
    if (d < 128) {
        long ko = ((long)(b * HKVN + h) * SS + s) * DHH;
        K[ko + 64 + d] = v;
    } else {
        long vo = ((long)(b * HKVN + h) * SS + s) * DVV;
        V[vo + d - 128] = v;
    }
}

// ---------------- causal flash attention (fp32) ----------------
// grid (S/64, H, B), 256 threads. BQ=BK=64.
#define BQ 64
#define BK 64
#define QSTR 196
#define VSTR 132
#define PSTR 66
#define ATTN_SMEM ((BQ*QSTR + BK*QSTR + BK*VSTR + BQ*PSTR) * 4)

__global__ void __launch_bounds__(256) flash_attn(
    const float* __restrict__ Qg, const float* __restrict__ Kg,
    const float* __restrict__ Vg, float* __restrict__ Og)
{
    extern __shared__ float sm[];
    float* Qs = sm;                 // [64][196]
    float* Ks = Qs + BQ * QSTR;     // [64][196]
    float* Vs = Ks + BK * QSTR;     // [64][132]
    float* Ps = Vs + BK * VSTR;     // [64][66]

    const int tid = threadIdx.x;
    const int bx = blockIdx.x, h = blockIdx.y, b = blockIdx.z;
    const int q0 = bx * BQ;
    const int kvh = h / GRP;

    const float* Qbase = Qg + ((long)(b * HH + h) * SS + q0) * DHH;
    const float* Kbase = Kg + ((long)(b * HKVN + kvh) * SS) * DHH;
    const float* Vbase = Vg + ((long)(b * HKVN + kvh) * SS) * DVV;

    for (int i = tid; i < BQ * 48; i += 256) {
        int r = i / 48, c4 = i % 48;
        *(float4*)&Qs[r * QSTR + c4 * 4] = *(const float4*)&Qbase[(long)r * DHH + c4 * 4];
    }

    const int trow = tid >> 3;   // 0..31 (2 rows each)
    const int tcol = tid & 7;    // 0..7

    float m[2], l[2], acc[2][16];
#pragma unroll
    for (int r = 0; r < 2; r++) {
        m[r] = -1e30f; l[r] = 0.f;
#pragma unroll
        for (int c = 0; c < 16; c++) acc[r][c] = 0.f;
    }

    const float scale = 0.07216878364870323f;  // 1/sqrt(192)

    for (int kb = 0; kb <= bx; kb++) {
        __syncthreads();
        const float* Kt = Kbase + (long)kb * BK * DHH;
        for (int i = tid; i < BK * 48; i += 256) {
            int r = i / 48, c4 = i % 48;
            *(float4*)&Ks[r * QSTR + c4 * 4] = *(const float4*)&Kt[(long)r * DHH + c4 * 4];
        }
        const float* Vt = Vbase + (long)kb * BK * DVV;
        for (int i = tid; i < BK * 32; i += 256) {
            int r = i / 32, c4 = i % 32;
            *(float4*)&Vs[r * VSTR + c4 * 4] = *(const float4*)&Vt[(long)r * DVV + c4 * 4];
        }
        __syncthreads();

        // ---- scores: 2x8 per thread over d=192 ----
        float s[2][8];
#pragma unroll
        for (int r = 0; r < 2; r++)
#pragma unroll
            for (int c = 0; c < 8; c++) s[r][c] = 0.f;

        for (int d = 0; d < DHH; d += 4) {
            float4 qv[2], kv[8];
#pragma unroll
            for (int r = 0; r < 2; r++)
                qv[r] = *(float4*)&Qs[(trow * 2 + r) * QSTR + d];
#pragma unroll
            for (int c = 0; c < 8; c++)
                kv[c] = *(float4*)&Ks[(tcol + 8 * c) * QSTR + d];
#pragma unroll
            for (int r = 0; r < 2; r++)
#pragma unroll
                for (int c = 0; c < 8; c++)
                    s[r][c] += qv[r].x * kv[c].x + qv[r].y * kv[c].y
                             + qv[r].z * kv[c].z + qv[r].w * kv[c].w;
        }

        // ---- online softmax ----
        const bool diag = (kb == bx);
#pragma unroll
        for (int r = 0; r < 2; r++) {
            int qg = q0 + trow * 2 + r;
            float rmax = -1e30f;
#pragma unroll
            for (int c = 0; c < 8; c++) {
                float v = s[r][c] * scale;
                if (diag) {
                    int kg = kb * BK + tcol + 8 * c;
                    if (kg > qg) v = -1e30f;
                }
                s[r][c] = v;
                rmax = fmaxf(rmax, v);
            }
            rmax = fmaxf(rmax, __shfl_xor_sync(0xffffffffu, rmax, 1));
            rmax = fmaxf(rmax, __shfl_xor_sync(0xffffffffu, rmax, 2));
            rmax = fmaxf(rmax, __shfl_xor_sync(0xffffffffu, rmax, 4));
            float mnew = fmaxf(m[r], rmax);
            float corr = __expf(m[r] - mnew);
            float psum = 0.f;
#pragma unroll
            for (int c = 0; c < 8; c++) {
                float p = __expf(s[r][c] - mnew);
                Ps[(trow * 2 + r) * PSTR + tcol + 8 * c] = p;
                psum += p;
            }
            psum += __shfl_xor_sync(0xffffffffu, psum, 1);
            psum += __shfl_xor_sync(0xffffffffu, psum, 2);
            psum += __shfl_xor_sync(0xffffffffu, psum, 4);
            l[r] = l[r] * corr + psum;
            m[r] = mnew;
#pragma unroll
            for (int c = 0; c < 16; c++) acc[r][c] *= corr;
        }
        __syncthreads();

        // ---- O += P @ V  (thread: 2 rows x 16 v-dims) ----
        for (int k = 0; k < BK; k++) {
            float4 v0 = *(float4*)&Vs[k * VSTR + tcol * 16];
            float4 v1 = *(float4*)&Vs[k * VSTR + tcol * 16 + 4];
            float4 v2 = *(float4*)&Vs[k * VSTR + tcol * 16 + 8];
            float4 v3 = *(float4*)&Vs[k * VSTR + tcol * 16 + 12];
#pragma unroll
            for (int r = 0; r < 2; r++) {
                float p = Ps[(trow * 2 + r) * PSTR + k];
                acc[r][0]  += p * v0.x; acc[r][1]  += p * v0.y;
                acc[r][2]  += p * v0.z; acc[r][3]  += p * v0.w;
                acc[r][4]  += p * v1.x; acc[r][5]  += p * v1.y;
                acc[r][6]  += p * v1.z; acc[r][7]  += p * v1.w;
                acc[r][8]  += p * v2.x; acc[r][9]  += p * v2.y;
                acc[r][10] += p * v2.z; acc[r][11] += p * v2.w;
                acc[r][12] += p * v3.x; acc[r][13] += p * v3.y;
                acc[r][14] += p * v3.z; acc[r][15] += p * v3.w;
            }
        }
    }

    // ---- epilogue ----
#pragma unroll
    for (int r = 0; r < 2; r++) {
        int qg = q0 + trow * 2 + r;
        float inv = 1.f / l[r];
        long o = ((long)b * SS + qg) * (HH * DVV) + h * DVV + tcol * 16;
#pragma unroll
        for (int c4 = 0; c4 < 4; c4++) {
            float4 v = make_float4(acc[r][c4*4+0] * inv, acc[r][c4*4+1] * inv,
                                   acc[r][c4*4+2] * inv, acc[r][c4*4+3] * inv);
            *(float4*)&Og[o + c4 * 4] = v;
        }
    }
}

// ---------------- launch ----------------
extern "C" void kernel_launch(void* const* d_in, const int* in_sizes, int n_in,
                              void* d_out, int out_size)
{
    const float* hidden = (const float*)d_in[0];
    const float* w_qa  = (const float*)d_in[2];
    const float* b_qa  = (const float*)d_in[3];
    const float* gq    = (const float*)d_in[4];
    const float* w_qb  = (const float*)d_in[5];
    const float* b_qb  = (const float*)d_in[6];
    const float* w_kva = (const float*)d_in[7];
    const float* b_kva = (const float*)d_in[8];
    const float* gkv   = (const float*)d_in[9];
    const float* w_kvb = (const float*)d_in[10];
    const float* b_kvb = (const float*)d_in[11];
    const float* w_o   = (const float*)d_in[12];
    const float* b_o   = (const float*)d_in[13];
    float* out = (float*)d_out;

    float *p_qa, *p_qn, *p_qb, *p_kva, *p_kvn, *p_kvb, *p_Q, *p_K, *p_V, *p_AO;
    cudaGetSymbolAddress((void**)&p_qa,  g_qa);
    cudaGetSymbolAddress((void**)&p_qn,  g_qn);
    cudaGetSymbolAddress((void**)&p_qb,  g_qb);
    cudaGetSymbolAddress((void**)&p_kva, g_kva);
    cudaGetSymbolAddress((void**)&p_kvn, g_kvn);
    cudaGetSymbolAddress((void**)&p_kvb, g_kvb);
    cudaGetSymbolAddress((void**)&p_Q,   g_Q);
    cudaGetSymbolAddress((void**)&p_K,   g_K);
    cudaGetSymbolAddress((void**)&p_V,   g_V);
    cudaGetSymbolAddress((void**)&p_AO,  g_AO);

    sgemm_bias<<<dim3(RQ/128, MM/128), 256>>>(hidden, w_qa, b_qa, p_qa, MM, RQ, DD);
    rmsnorm_k<<<MM, 256>>>(p_qa, RQ, gq, p_qn, RQ);
    sgemm_bias<<<dim3((HH*DHH)/128, MM/128), 256>>>(p_qn, w_qb, b_qb, p_qb, MM, HH*DHH, RQ);
    sgemm_bias<<<dim3((RKV+DR+127)/128, MM/128), 256>>>(hidden, w_kva, b_kva, p_kva, MM, RKV+DR, DD);
    rmsnorm_k<<<MM, 256>>>(p_kva, RKV+DR, gkv, p_kvn, RKV);
    sgemm_bias<<<dim3((HKVN*256)/128, MM/128), 256>>>(p_kvn, w_kvb, b_kvb, p_kvb, MM, HKVN*256, RKV);

    build_q_rope <<<(BB*HH*SS*32   + 255)/256, 256>>>(p_qb, p_Q);
    build_q_nrope<<<(BB*HH*SS*128  + 255)/256, 256>>>(p_qb, p_Q);
    build_k_rope <<<(BB*HKVN*SS*32 + 255)/256, 256>>>(p_kva, p_K);
    build_kv     <<<(BB*HKVN*SS*256+ 255)/256, 256>>>(p_kvb, p_K, p_V);

    cudaFuncSetAttribute(flash_attn, cudaFuncAttributeMaxDynamicSharedMemorySize, ATTN_SMEM);
    flash_attn<<<dim3(SS/BQ, HH, BB), 256, ATTN_SMEM>>>(p_Q, p_K, p_V, p_AO);

    sgemm_bias<<<dim3(DD/128, MM/128), 256>>>(p_AO, w_o, b_o, out, MM, DD, HH*DVV);
}

// round 8
// speedup vs baseline: 1.0061x; 1.0061x over previous
#include <cuda_runtime.h>
#include <math.h>
#include <stdint.h>

// ---------------- problem constants ----------------
#define BB   2
#define SS   2048
#define DD   2048
#define HH   16
#define HKVN 4
#define GRP  4          // HH / HKVN
#define RQ   1024
#define RKV  512
#define DR   64
#define DN   128
#define DHH  192        // DR + DN
#define DVV  128
#define MM   (BB*SS)    // 4096 rows

// ---------------- scratch (device globals; no allocation allowed) ---------
__device__ float g_qa [MM*RQ];
__device__ float g_qn [MM*RQ];
__device__ float g_qb [MM*HH*DHH];
__device__ float g_kva[MM*(RKV+DR)];
__device__ float g_kvn[MM*RKV];
__device__ float g_kvb[MM*HKVN*(DN+DVV)];
__device__ float g_Q  [(long)BB*HH*SS*DHH];
__device__ float g_K  [(long)BB*HKVN*SS*DHH];
__device__ float g_V  [(long)BB*HKVN*SS*DVV];
__device__ float g_AO [MM*HH*DVV];

// ---------------- tf32 helpers ----------------
__device__ __forceinline__ uint32_t f2tf32(float f) {
    uint32_t r;
    asm("cvt.rna.tf32.f32 %0, %1;" : "=r"(r) : "f"(f));
    return r;
}

__device__ __forceinline__ void mma_tf32(float* c, const uint32_t* a, const uint32_t* b) {
    asm volatile(
        "mma.sync.aligned.m16n8k8.row.col.f32.tf32.tf32.f32 "
        "{%0,%1,%2,%3}, {%4,%5,%6,%7}, {%8,%9}, {%0,%1,%2,%3};"
        : "+f"(c[0]), "+f"(c[1]), "+f"(c[2]), "+f"(c[3])
        : "r"(a[0]), "r"(a[1]), "r"(a[2]), "r"(a[3]), "r"(b[0]), "r"(b[1]));
}

// ---------------- 3xTF32 tensor-core GEMM: C = A[M,K] @ B[K,N] + bias ------
// 128x128x16 tile, 256 threads (8 warps, 4x2), each warp 32x64 via m16n8k8.
// Split precision: a = hi + lo; acc += hi*hi + hi*lo + lo*hi  (~fp32 accuracy).
// Requires M % 128 == 0, K % 16 == 0, N % 8 == 0 (N tile-bound guarded).
#define GK 16
#define GSTR 132
// smem plane index, call order (ptr, plane, buf, k, col); planes: 0=Ahi 1=Alo 2=Bhi 3=Blo
#define SPL(p, pl, buf, k, c) p[((((buf)*4 + (pl))*GK + (k))*GSTR) + (c)]
#define GEMM_SMEM (2*4*GK*GSTR*4)

__global__ void __launch_bounds__(256) sgemm_tf32(
    const float* __restrict__ A, const float* __restrict__ Bm,
    const float* __restrict__ bias, float* __restrict__ C,
    int M, int N, int K)
{
    extern __shared__ uint32_t smu[];

    const int tid = threadIdx.x;
    const int bm  = blockIdx.y * 128;
    const int bn  = blockIdx.x * 128;

    const int wid = tid >> 5;
    const int lane = tid & 31;
    const int lr = lane >> 2;      // 0..7
    const int lc = lane & 3;       // 0..3
    const int wm = wid & 3;        // 4 warps over M -> 32 rows each
    const int wn = wid >> 2;       // 2 warps over N -> 64 cols each

    // global load mapping
    const int arow = tid >> 1;          // 0..127
    const int acol = (tid & 1) * 8;     // 0 / 8
    const int brow = tid >> 4;          // 0..15
    const int bcol = (tid & 15) * 8;    // 0..120

    const long Abase = (long)(bm + arow) * K + acol;
    const bool bok = (bn + bcol < N);

    float acc[2][8][4];
#pragma unroll
    for (int i = 0; i < 2; i++)
#pragma unroll
        for (int j = 0; j < 8; j++)
#pragma unroll
            for (int t = 0; t < 4; t++) acc[i][j][t] = 0.f;

    // ---- stage a K-tile into smem (hi/lo split) ----
    auto stage = [&](int sbuf, int k0) {
        float4 a0 = *(const float4*)&A[Abase + k0];
        float4 a1 = *(const float4*)&A[Abase + k0 + 4];
        float av[8] = {a0.x,a0.y,a0.z,a0.w,a1.x,a1.y,a1.z,a1.w};
#pragma unroll
        for (int j = 0; j < 8; j++) {
            uint32_t hi = f2tf32(av[j]);
            uint32_t lo = f2tf32(av[j] - __uint_as_float(hi));
            SPL(smu, 0, sbuf, acol + j, arow) = hi;
            SPL(smu, 1, sbuf, acol + j, arow) = lo;
        }
        float4 b0 = make_float4(0.f,0.f,0.f,0.f), b1 = b0;
        if (bok) {
            b0 = *(const float4*)&Bm[(long)(k0 + brow) * N + bn + bcol];
            b1 = *(const float4*)&Bm[(long)(k0 + brow) * N + bn + bcol + 4];
        }
        float bv[8] = {b0.x,b0.y,b0.z,b0.w,b1.x,b1.y,b1.z,b1.w};
#pragma unroll
        for (int j = 0; j < 8; j++) {
            uint32_t hi = f2tf32(bv[j]);
            uint32_t lo = f2tf32(bv[j] - __uint_as_float(hi));
            SPL(smu, 2, sbuf, brow, bcol + j) = hi;
            SPL(smu, 3, sbuf, brow, bcol + j) = lo;
        }
    };

    stage(0, 0);
    __syncthreads();

    int buf = 0;
    for (int k0 = GK; k0 <= K; k0 += GK) {
        const bool more = (k0 < K);

        // compute on current buffer
#pragma unroll
        for (int ks = 0; ks < 2; ks++) {
            const int kk = ks * 8;
            uint32_t ah[2][4], al[2][4];
#pragma unroll
            for (int i = 0; i < 2; i++) {
                int m0 = wm * 32 + i * 16 + lr;
                ah[i][0] = SPL(smu, 0, buf, kk + lc,     m0);
                ah[i][1] = SPL(smu, 0, buf, kk + lc,     m0 + 8);
                ah[i][2] = SPL(smu, 0, buf, kk + lc + 4, m0);
                ah[i][3] = SPL(smu, 0, buf, kk + lc + 4, m0 + 8);
                al[i][0] = SPL(smu, 1, buf, kk + lc,     m0);
                al[i][1] = SPL(smu, 1, buf, kk + lc,     m0 + 8);
                al[i][2] = SPL(smu, 1, buf, kk + lc + 4, m0);
                al[i][3] = SPL(smu, 1, buf, kk + lc + 4, m0 + 8);
            }
#pragma unroll
            for (int j = 0; j < 8; j++) {
                int n0 = wn * 64 + j * 8 + lr;
                uint32_t bh[2], bl[2];
                bh[0] = SPL(smu, 2, buf, kk + lc,     n0);
                bh[1] = SPL(smu, 2, buf, kk + lc + 4, n0);
                bl[0] = SPL(smu, 3, buf, kk + lc,     n0);
                bl[1] = SPL(smu, 3, buf, kk + lc + 4, n0);
#pragma unroll
                for (int i = 0; i < 2; i++) {
                    mma_tf32(acc[i][j], ah[i], bh);   // hi*hi
                    mma_tf32(acc[i][j], ah[i], bl);   // hi*lo
                    mma_tf32(acc[i][j], al[i], bh);   // lo*hi
                }
            }
        }

        if (more) {
            stage(buf ^ 1, k0);
            __syncthreads();
            buf ^= 1;
        }
    }

    // ---- epilogue: c0:(lr, 2lc) c1:(lr, 2lc+1) c2:(lr+8,·) c3 ----
#pragma unroll
    for (int i = 0; i < 2; i++) {
#pragma unroll
        for (int j = 0; j < 8; j++) {
            int row0 = bm + wm * 32 + i * 16 + lr;
            int col  = bn + wn * 64 + j * 8 + lc * 2;
            if (col < N) {
                float2 bz = *(const float2*)&bias[col];
                float2 v0 = make_float2(acc[i][j][0] + bz.x, acc[i][j][1] + bz.y);
                float2 v1 = make_float2(acc[i][j][2] + bz.x, acc[i][j][3] + bz.y);
                *(float2*)&C[(long)row0 * N + col]       = v0;
                *(float2*)&C[(long)(row0 + 8) * N + col] = v1;
            }
        }
    }
}

// ---------------- RMSNorm (per row) ----------------
__global__ void __launch_bounds__(256) rmsnorm_k(
    const float* __restrict__ in, int inStride,
    const float* __restrict__ g, float* __restrict__ out, int L)
{
    const long row = blockIdx.x;
    const float* x = in + row * inStride;
    float s = 0.f;
    for (int i = threadIdx.x; i < L; i += 256) { float v = x[i]; s += v * v; }
#pragma unroll
    for (int o = 16; o > 0; o >>= 1) s += __shfl_xor_sync(0xffffffffu, s, o);
    __shared__ float red[8];
    if ((threadIdx.x & 31) == 0) red[threadIdx.x >> 5] = s;
    __syncthreads();
    float tot = 0.f;
#pragma unroll
    for (int i = 0; i < 8; i++) tot += red[i];
    const float sc = rsqrtf(tot / (float)L + 1e-20f);
    for (int i = threadIdx.x; i < L; i += 256)
        out[row * L + i] = x[i] * sc * g[i];
}

// ---------------- RoPE helpers / layout builders ----------------
__device__ __forceinline__ void rope_cs(int s, int j, float& c, float& sn) {
    float inv = (float)exp(-(double)j / 32.0 * log(10000.0));
    float a = (float)s * inv;
    c = cosf(a); sn = sinf(a);
}

__global__ void build_q_rope(const float* __restrict__ qb, float* __restrict__ Q)
{
    int idx = blockIdx.x * blockDim.x + threadIdx.x;
    if (idx >= BB * HH * SS * 32) return;
    int j = idx & 31; int t = idx >> 5;
    int s = t % SS; int t2 = t / SS;
    int h = t2 % HH; int b = t2 / HH;
    long base = (long)(b * SS + s) * (HH * DHH) + h * DHH;
    float x1 = qb[base + DN + j];
    float x2 = qb[base + DN + 32 + j];
    float c, sn; rope_cs(s, j, c, sn);
    long qo = ((long)(b * HH + h) * SS + s) * DHH;
    Q[qo + j]      = x1 * c - x2 * sn;
    Q[qo + 32 + j] = x2 * c + x1 * sn;
}

__global__ void build_q_nrope(const float* __restrict__ qb, float* __restrict__ Q)
{
    int idx = blockIdx.x * blockDim.x + threadIdx.x;
    if (idx >= BB * HH * SS * 128) return;
    int d = idx & 127; int t = idx >> 7;
    int s = t % SS; int t2 = t / SS;
    int h = t2 % HH; int b = t2 / HH;
    long base = (long)(b * SS + s) * (HH * DHH) + h * DHH;
    long qo = ((long)(b * HH + h) * SS + s) * DHH;
    Q[qo + 64 + d] = qb[base + d];
}

__global__ void build_k_rope(const float* __restrict__ kva, float* __restrict__ K)
{
    int idx = blockIdx.x * blockDim.x + threadIdx.x;
    if (idx >= BB * HKVN * SS * 32) return;
    int j = idx & 31; int t = idx >> 5;
    int s = t % SS; int t2 = t / SS;
    int h = t2 % HKVN; int b = t2 / HKVN;
    long base = (long)(b * SS + s) * (RKV + DR) + RKV;
    float x1 = kva[base + j];
    float x2 = kva[base + 32 + j];
    float c, sn; rope_cs(s, j, c, sn);
    long ko = ((long)(b * HKVN + h) * SS + s) * DHH;
    K[ko + j]      = x1 * c - x2 * sn;
    K[ko + 32 + j] = x2 * c + x1 * sn;
}

__global__ void build_kv(const float* __restrict__ kvb,
                         float* __restrict__ K, float* __restrict__ V)
{
    int idx = blockIdx.x * blockDim.x + threadIdx.x;
    if (idx >= BB * HKVN * SS * 256) return;
    int d = idx & 255; int t = idx >> 8;
    int s = t % SS; int t2 = t / SS;
    int h = t2 % HKVN; int b = t2 / HKVN;
    float v = kvb[(long)(b * SS + s) * (HKVN * 256) + h * 256 + d];
    if (d < 128) {
        long ko = ((long)(b * HKVN + h) * SS + s) * DHH;
        K[ko + 64 + d] = v;
    } else {
        long vo = ((long)(b * HKVN + h) * SS + s) * DVV;
        V[vo + d - 128] = v;
    }
}

// ---------------- causal flash attention (fp32) ----------------
#define BQ 64
#define BK 64
#define QSTR 196
#define VSTR 132
#define PSTR 66
#define ATTN_SMEM ((BQ*QSTR + BK*QSTR + BK*VSTR + BQ*PSTR) * 4)

__global__ void __launch_bounds__(256) flash_attn(
    const float* __restrict__ Qg, const float* __restrict__ Kg,
    const float* __restrict__ Vg, float* __restrict__ Og)
{
    extern __shared__ float sm[];
    float* Qs = sm;                 // [64][196]
    float* Ks = Qs + BQ * QSTR;     // [64][196]
    float* Vs = Ks + BK * QSTR;     // [64][132]
    float* Ps = Vs + BK * VSTR;     // [64][66]

    const int tid = threadIdx.x;
    const int bx = blockIdx.x, h = blockIdx.y, b = blockIdx.z;
    const int q0 = bx * BQ;
    const int kvh = h / GRP;

    const float* Qbase = Qg + ((long)(b * HH + h) * SS + q0) * DHH;
    const float* Kbase = Kg + ((long)(b * HKVN + kvh) * SS) * DHH;
    const float* Vbase = Vg + ((long)(b * HKVN + kvh) * SS) * DVV;

    for (int i = tid; i < BQ * 48; i += 256) {
        int r = i / 48, c4 = i % 48;
        *(float4*)&Qs[r * QSTR + c4 * 4] = *(const float4*)&Qbase[(long)r * DHH + c4 * 4];
    }

    const int trow = tid >> 3;   // 0..31 (2 rows each)
    const int tcol = tid & 7;    // 0..7

    float m[2], l[2], acc[2][16];
#pragma unroll
    for (int r = 0; r < 2; r++) {
        m[r] = -1e30f; l[r] = 0.f;
#pragma unroll
        for (int c = 0; c < 16; c++) acc[r][c] = 0.f;
    }

    const float scale = 0.07216878364870323f;  // 1/sqrt(192)

    for (int kb = 0; kb <= bx; kb++) {
        __syncthreads();
        const float* Kt = Kbase + (long)kb * BK * DHH;
        for (int i = tid; i < BK * 48; i += 256) {
            int r = i / 48, c4 = i % 48;
            *(float4*)&Ks[r * QSTR + c4 * 4] = *(const float4*)&Kt[(long)r * DHH + c4 * 4];
        }
        const float* Vt = Vbase + (long)kb * BK * DVV;
        for (int i = tid; i < BK * 32; i += 256) {
            int r = i / 32, c4 = i % 32;
            *(float4*)&Vs[r * VSTR + c4 * 4] = *(const float4*)&Vt[(long)r * DVV + c4 * 4];
        }
        __syncthreads();

        float s[2][8];
#pragma unroll
        for (int r = 0; r < 2; r++)
#pragma unroll
            for (int c = 0; c < 8; c++) s[r][c] = 0.f;

        for (int d = 0; d < DHH; d += 4) {
            float4 qv[2], kv[8];
#pragma unroll
            for (int r = 0; r < 2; r++)
                qv[r] = *(float4*)&Qs[(trow * 2 + r) * QSTR + d];
#pragma unroll
            for (int c = 0; c < 8; c++)
                kv[c] = *(float4*)&Ks[(tcol + 8 * c) * QSTR + d];
#pragma unroll
            for (int r = 0; r < 2; r++)
#pragma unroll
                for (int c = 0; c < 8; c++)
                    s[r][c] += qv[r].x * kv[c].x + qv[r].y * kv[c].y
                             + qv[r].z * kv[c].z + qv[r].w * kv[c].w;
        }

        const bool diag = (kb == bx);
#pragma unroll
        for (int r = 0; r < 2; r++) {
            int qg = q0 + trow * 2 + r;
            float rmax = -1e30f;
#pragma unroll
            for (int c = 0; c < 8; c++) {
                float v = s[r][c] * scale;
                if (diag) {
                    int kg = kb * BK + tcol + 8 * c;
                    if (kg > qg) v = -1e30f;
                }
                s[r][c] = v;
                rmax = fmaxf(rmax, v);
            }
            rmax = fmaxf(rmax, __shfl_xor_sync(0xffffffffu, rmax, 1));
            rmax = fmaxf(rmax, __shfl_xor_sync(0xffffffffu, rmax, 2));
            rmax = fmaxf(rmax, __shfl_xor_sync(0xffffffffu, rmax, 4));
            float mnew = fmaxf(m[r], rmax);
            float corr = __expf(m[r] - mnew);
            float psum = 0.f;
#pragma unroll
            for (int c = 0; c < 8; c++) {
                float p = __expf(s[r][c] - mnew);
                Ps[(trow * 2 + r) * PSTR + tcol + 8 * c] = p;
                psum += p;
            }
            psum += __shfl_xor_sync(0xffffffffu, psum, 1);
            psum += __shfl_xor_sync(0xffffffffu, psum, 2);
            psum += __shfl_xor_sync(0xffffffffu, psum, 4);
            l[r] = l[r] * corr + psum;
            m[r] = mnew;
#pragma unroll
            for (int c = 0; c < 16; c++) acc[r][c] *= corr;
        }
        __syncthreads();

        for (int k = 0; k < BK; k++) {
            float4 v0 = *(float4*)&Vs[k * VSTR + tcol * 16];
            float4 v1 = *(float4*)&Vs[k * VSTR + tcol * 16 + 4];
            float4 v2 = *(float4*)&Vs[k * VSTR + tcol * 16 + 8];
            float4 v3 = *(float4*)&Vs[k * VSTR + tcol * 16 + 12];
#pragma unroll
            for (int r = 0; r < 2; r++) {
                float p = Ps[(trow * 2 + r) * PSTR + k];
                acc[r][0]  += p * v0.x; acc[r][1]  += p * v0.y;
                acc[r][2]  += p * v0.z; acc[r][3]  += p * v0.w;
                acc[r][4]  += p * v1.x; acc[r][5]  += p * v1.y;
                acc[r][6]  += p * v1.z; acc[r][7]  += p * v1.w;
                acc[r][8]  += p * v2.x; acc[r][9]  += p * v2.y;
                acc[r][10] += p * v2.z; acc[r][11] += p * v2.w;
                acc[r][12] += p * v3.x; acc[r][13] += p * v3.y;
                acc[r][14] += p * v3.z; acc[r][15] += p * v3.w;
            }
        }
    }

#pragma unroll
    for (int r = 0; r < 2; r++) {
        int qg = q0 + trow * 2 + r;
        float inv = 1.f / l[r];
        long o = ((long)b * SS + qg) * (HH * DVV) + h * DVV + tcol * 16;
#pragma unroll
        for (int c4 = 0; c4 < 4; c4++) {
            float4 v = make_float4(acc[r][c4*4+0] * inv, acc[r][c4*4+1] * inv,
                                   acc[r][c4*4+2] * inv, acc[r][c4*4+3] * inv);
            *(float4*)&Og[o + c4 * 4] = v;
        }
    }
}

// ---------------- launch ----------------
extern "C" void kernel_launch(void* const* d_in, const int* in_sizes, int n_in,
                              void* d_out, int out_size)
{
    const float* hidden = (const float*)d_in[0];
    const float* w_qa  = (const float*)d_in[2];
    const float* b_qa  = (const float*)d_in[3];
    const float* gq    = (const float*)d_in[4];
    const float* w_qb  = (const float*)d_in[5];
    const float* b_qb  = (const float*)d_in[6];
    const float* w_kva = (const float*)d_in[7];
    const float* b_kva = (const float*)d_in[8];
    const float* gkv   = (const float*)d_in[9];
    const float* w_kvb = (const float*)d_in[10];
    const float* b_kvb = (const float*)d_in[11];
    const float* w_o   = (const float*)d_in[12];
    const float* b_o   = (const float*)d_in[13];
    float* out = (float*)d_out;

    float *p_qa, *p_qn, *p_qb, *p_kva, *p_kvn, *p_kvb, *p_Q, *p_K, *p_V, *p_AO;
    cudaGetSymbolAddress((void**)&p_qa,  g_qa);
    cudaGetSymbolAddress((void**)&p_qn,  g_qn);
    cudaGetSymbolAddress((void**)&p_qb,  g_qb);
    cudaGetSymbolAddress((void**)&p_kva, g_kva);
    cudaGetSymbolAddress((void**)&p_kvn, g_kvn);
    cudaGetSymbolAddress((void**)&p_kvb, g_kvb);
    cudaGetSymbolAddress((void**)&p_Q,   g_Q);
    cudaGetSymbolAddress((void**)&p_K,   g_K);
    cudaGetSymbolAddress((void**)&p_V,   g_V);
    cudaGetSymbolAddress((void**)&p_AO,  g_AO);

    cudaFuncSetAttribute(sgemm_tf32, cudaFuncAttributeMaxDynamicSharedMemorySize, GEMM_SMEM);

    sgemm_tf32<<<dim3(RQ/128, MM/128), 256, GEMM_SMEM>>>(hidden, w_qa, b_qa, p_qa, MM, RQ, DD);
    rmsnorm_k<<<MM, 256>>>(p_qa, RQ, gq, p_qn, RQ);
    sgemm_tf32<<<dim3((HH*DHH)/128, MM/128), 256, GEMM_SMEM>>>(p_qn, w_qb, b_qb, p_qb, MM, HH*DHH, RQ);
    sgemm_tf32<<<dim3((RKV+DR+127)/128, MM/128), 256, GEMM_SMEM>>>(hidden, w_kva, b_kva, p_kva, MM, RKV+DR, DD);
    rmsnorm_k<<<MM, 256>>>(p_kva, RKV+DR, gkv, p_kvn, RKV);
    sgemm_tf32<<<dim3((HKVN*256)/128, MM/128), 256, GEMM_SMEM>>>(p_kvn, w_kvb, b_kvb, p_kvb, MM, HKVN*256, RKV);

    build_q_rope <<<(BB*HH*SS*32   + 255)/256, 256>>>(p_qb, p_Q);
    build_q_nrope<<<(BB*HH*SS*128  + 255)/256, 256>>>(p_qb, p_Q);
    build_k_rope <<<(BB*HKVN*SS*32 + 255)/256, 256>>>(p_kva, p_K);
    build_kv     <<<(BB*HKVN*SS*256+ 255)/256, 256>>>(p_kvb, p_K, p_V);

    cudaFuncSetAttribute(flash_attn, cudaFuncAttributeMaxDynamicSharedMemorySize, ATTN_SMEM);
    flash_attn<<<dim3(SS/BQ, HH, BB), 256, ATTN_SMEM>>>(p_Q, p_K, p_V, p_AO);

    sgemm_tf32<<<dim3(DD/128, MM/128), 256, GEMM_SMEM>>>(p_AO, w_o, b_o, out, MM, DD, HH*DVV);
}